// round 3
// baseline (speedup 1.0000x reference)
#include <cuda_runtime.h>
#include <math.h>

#define BB   4
#define NN   50000
#define CC   64
#define EE   800000
#define NLBL 10000
#define RR   (NN*BB)        /* 200000 GEMM rows (node,batch) */
#define ROWF (BB*CC)        /* 256 floats per node across batches */
#define NTILES (RR/32)      /* 6250 */

// ---------------- device scratch (no allocations allowed) ----------------
__device__ float g_X[2][RR*CC];     // ping-pong node state, 2 x 51.2MB
__device__ float g_X0[RR*CC];       // initial features (needed for attention)
__device__ float g_AGG[RR*CC];      // neighbor sums
__device__ float g_P[5*64*192];     // P[l] = ggc[l] @ w_ih^T, [k][j] layout
__device__ float g_WHH[64*192];     // w_hh^T, [k][j]
__device__ float g_AIW[128*128];    // ai_w^T, [k][j]
__device__ float g_AJW[128*128];    // aj_w^T, [k][j]
__device__ float g_POOL[512];       // att pooled sums [b][128]

__device__ __forceinline__ float sigm(float v) { return 1.0f / (1.0f + expf(-v)); }

// ---------------- prep kernels ----------------
__global__ void k_prep_P(const float* __restrict__ ggc, const float* __restrict__ w_ih) {
    int idx = blockIdx.x * 256 + threadIdx.x;
    if (idx >= 5 * 64 * 192) return;
    int l = idx / (64 * 192);
    int rem = idx % (64 * 192);
    int k = rem / 192, j = rem % 192;
    const float* a = ggc + (l * 64 + k) * 64;
    const float* w = w_ih + j * 64;
    float s = 0.f;
#pragma unroll 8
    for (int c = 0; c < 64; c++) s += a[c] * w[c];
    g_P[idx] = s;
}

__global__ void k_prep_T(const float* __restrict__ w_hh,
                         const float* __restrict__ ai_w,
                         const float* __restrict__ aj_w) {
    int idx = blockIdx.x * 256 + threadIdx.x;
    if (idx < 12288) {
        int k = idx / 192, j = idx % 192;
        g_WHH[idx] = w_hh[j * 64 + k];
    } else if (idx < 12288 + 16384) {
        int i = idx - 12288;
        int k = i / 128, j = i % 128;
        g_AIW[i] = ai_w[j * 128 + k];
    } else if (idx < 12288 + 32768) {
        int i = idx - 28672;
        int k = i / 128, j = i % 128;
        g_AJW[i] = aj_w[j * 128 + k];
    }
}

__global__ void k_init(const float* __restrict__ nodes) {
    int n = blockIdx.x;
    int t = threadIdx.x;          // 0..255 -> (b,c)
    int c = t & 63;
    float v = (c < 63) ? nodes[n * 63 + c] : 0.f;
    int idx = n * ROWF + t;
    g_X0[idx] = v;
    g_X[0][idx] = v;
}

__global__ void k_cov(const float* __restrict__ cov, const int* __restrict__ c2l) {
    int idx = blockIdx.x * 256 + threadIdx.x;
    if (idx >= BB * NLBL) return;
    int b = idx / NLBL, j = idx % NLBL;
    int lbl = c2l[j];
    float v = cov[idx];
    int pos = lbl * ROWF + b * 64 + 63;
    g_X0[pos] = v;
    g_X[0][pos] = v;
}

__global__ void k_zero_agg() {
    int idx = blockIdx.x * 256 + threadIdx.x;   // 12500*256 = RR*CC/4
    ((float4*)g_AGG)[idx] = make_float4(0.f, 0.f, 0.f, 0.f);
}

__global__ void k_zero_pool() {
    int idx = blockIdx.x * 256 + threadIdx.x;
    if (idx < 512) g_POOL[idx] = 0.f;
}

// ---------------- edge scatter: AGG[dst] += X[src], all 4 batches ----------------
__global__ void k_scatter(const int* __restrict__ edges, int sel) {
    unsigned gid = blockIdx.x * 256u + threadIdx.x;
    int e = gid >> 6;           // 64 threads per edge (1KB row)
    int q = gid & 63;           // float4 index within row
    if (e >= EE) return;
    int src = edges[e];
    int dst = edges[EE + e];
    const float4 v = *(const float4*)(g_X[sel] + src * ROWF + q * 4);
    float* d = g_AGG + dst * ROWF + q * 4;
    atomicAdd(d + 0, v.x);
    atomicAdd(d + 1, v.y);
    atomicAdd(d + 2, v.z);
    atomicAdd(d + 3, v.w);
}

// ---------------- fused GGC+GRU layer: x_new = GRU(AGG @ P, x) ----------------
// tile: 32 rows x 192 cols, two GEMMs (gx from AGG, gh from x) fused, K=64.
// 256 threads: warp w owns local rows [w*4, w*4+4); lane owns cols lane*2+{0,1}+64t, t<3.
#define GRU_TILES 8
__global__ void __launch_bounds__(256, 1)
k_gru(const float* __restrict__ b_ih, const float* __restrict__ b_hh, int layer, int sel) {
    extern __shared__ float sm[];
    float* sP = sm;               // 64*192
    float* sW = sm + 12288;       // 64*192
    float* sA = sm + 24576;       // [64][36] aggT
    float* sX = sA + 64 * 36;     // [64][36] xT

    const float* P  = g_P + layer * 12288;
    const float* Xc = g_X[sel];
    float*       Xn = g_X[sel ^ 1];

    int tid = threadIdx.x, lane = tid & 31, warp = tid >> 5;

    for (int i = tid; i < 3072; i += 256) {
        ((float4*)sP)[i] = ((const float4*)P)[i];
        ((float4*)sW)[i] = ((const float4*)g_WHH)[i];
    }
    float bi[3][2], bh[3][2];
#pragma unroll
    for (int t = 0; t < 3; t++) {
        bi[t][0] = b_ih[64 * t + lane * 2];
        bi[t][1] = b_ih[64 * t + lane * 2 + 1];
        bh[t][0] = b_hh[64 * t + lane * 2];
        bh[t][1] = b_hh[64 * t + lane * 2 + 1];
    }
    __syncthreads();

    for (int it = 0; it < GRU_TILES; it++) {
        int tile = blockIdx.x * GRU_TILES + it;
        bool valid = tile < NTILES;
        int row0 = tile * 32;
        if (valid) {
#pragma unroll
            for (int iter = 0; iter < 2; iter++) {
                int k4 = warp + iter * 8;   // float4 chunk of k
                const float4 va = *(const float4*)(g_AGG + (row0 + lane) * CC + k4 * 4);
                const float4 vx = *(const float4*)(Xc    + (row0 + lane) * CC + k4 * 4);
                sA[(k4 * 4 + 0) * 36 + lane] = va.x;
                sA[(k4 * 4 + 1) * 36 + lane] = va.y;
                sA[(k4 * 4 + 2) * 36 + lane] = va.z;
                sA[(k4 * 4 + 3) * 36 + lane] = va.w;
                sX[(k4 * 4 + 0) * 36 + lane] = vx.x;
                sX[(k4 * 4 + 1) * 36 + lane] = vx.y;
                sX[(k4 * 4 + 2) * 36 + lane] = vx.z;
                sX[(k4 * 4 + 3) * 36 + lane] = vx.w;
            }
        }
        __syncthreads();
        if (valid) {
            float ax[4][3][2] = {};
            float ah[4][3][2] = {};
#pragma unroll 2
            for (int k = 0; k < 64; k++) {
                float4 a4 = *(const float4*)&sA[k * 36 + warp * 4];
                float4 x4 = *(const float4*)&sX[k * 36 + warp * 4];
                float2 p0 = *(const float2*)&sP[k * 192 +       lane * 2];
                float2 p1 = *(const float2*)&sP[k * 192 +  64 + lane * 2];
                float2 p2 = *(const float2*)&sP[k * 192 + 128 + lane * 2];
                float2 w0 = *(const float2*)&sW[k * 192 +       lane * 2];
                float2 w1 = *(const float2*)&sW[k * 192 +  64 + lane * 2];
                float2 w2 = *(const float2*)&sW[k * 192 + 128 + lane * 2];
                float aa[4] = {a4.x, a4.y, a4.z, a4.w};
                float xx[4] = {x4.x, x4.y, x4.z, x4.w};
                float pv[3][2] = {{p0.x, p0.y}, {p1.x, p1.y}, {p2.x, p2.y}};
                float wv[3][2] = {{w0.x, w0.y}, {w1.x, w1.y}, {w2.x, w2.y}};
#pragma unroll
                for (int nd = 0; nd < 4; nd++)
#pragma unroll
                    for (int t = 0; t < 3; t++)
#pragma unroll
                        for (int c2 = 0; c2 < 2; c2++) {
                            ax[nd][t][c2] += aa[nd] * pv[t][c2];
                            ah[nd][t][c2] += xx[nd] * wv[t][c2];
                        }
            }
#pragma unroll
            for (int nd = 0; nd < 4; nd++) {
                int row = row0 + warp * 4 + nd;
                float2 h2 = *(const float2*)&Xc[row * CC + lane * 2];
                float hv[2] = {h2.x, h2.y};
                float o[2];
#pragma unroll
                for (int c2 = 0; c2 < 2; c2++) {
                    float r  = sigm(ax[nd][0][c2] + bi[0][c2] + ah[nd][0][c2] + bh[0][c2]);
                    float z  = sigm(ax[nd][1][c2] + bi[1][c2] + ah[nd][1][c2] + bh[1][c2]);
                    float nn = tanhf(ax[nd][2][c2] + bi[2][c2] + r * (ah[nd][2][c2] + bh[2][c2]));
                    o[c2] = (1.f - z) * nn + z * hv[c2];
                }
                *(float2*)&Xn[row * CC + lane * 2] = make_float2(o[0], o[1]);
            }
        }
        __syncthreads();
    }
}

// ---------------- attention + pooling ----------------
// cat = [x, x0] (K=128); a_i = sigmoid(cat@ai_w^T+b), a_j = relu(cat@aj_w^T+b)
// POOL[b][j] += a_i*a_j summed over nodes. rows are (n*4+b) so b == local row % 4.
__global__ void __launch_bounds__(256, 1)
k_att(const float* __restrict__ ai_b, const float* __restrict__ aj_b, int sel) {
    extern __shared__ float sm[];
    float* sAI = sm;              // 128*128
    float* sAJ = sm + 16384;      // 128*128
    float* sC  = sm + 32768;      // [128][36] catT, reused for reduction (4096 < 4608)

    const float* Xf = g_X[sel];
    int tid = threadIdx.x, lane = tid & 31, warp = tid >> 5;

    for (int i = tid; i < 4096; i += 256) {
        ((float4*)sAI)[i] = ((const float4*)g_AIW)[i];
        ((float4*)sAJ)[i] = ((const float4*)g_AJW)[i];
    }
    float aib[2][2], ajb[2][2];
#pragma unroll
    for (int t = 0; t < 2; t++) {
        aib[t][0] = ai_b[64 * t + lane * 2];
        aib[t][1] = ai_b[64 * t + lane * 2 + 1];
        ajb[t][0] = aj_b[64 * t + lane * 2];
        ajb[t][1] = aj_b[64 * t + lane * 2 + 1];
    }
    float asum[4][2][2] = {};    // [b][t][c2]
    __syncthreads();

    for (int it = 0; it < 8; it++) {
        int tile = blockIdx.x * 8 + it;
        bool valid = tile < NTILES;
        int row0 = tile * 32;
        if (valid) {
#pragma unroll
            for (int iter = 0; iter < 4; iter++) {
                int k0 = (warp + iter * 8) * 4;     // 0..124
                float4 v = (k0 < 64)
                    ? *(const float4*)(Xf   + (row0 + lane) * CC + k0)
                    : *(const float4*)(g_X0 + (row0 + lane) * CC + k0 - 64);
                sC[(k0 + 0) * 36 + lane] = v.x;
                sC[(k0 + 1) * 36 + lane] = v.y;
                sC[(k0 + 2) * 36 + lane] = v.z;
                sC[(k0 + 3) * 36 + lane] = v.w;
            }
        }
        __syncthreads();
        if (valid) {
            float ai[4][2][2] = {};
            float aj[4][2][2] = {};
#pragma unroll 2
            for (int k = 0; k < 128; k++) {
                float4 c4 = *(const float4*)&sC[k * 36 + warp * 4];
                float2 i0 = *(const float2*)&sAI[k * 128 +      lane * 2];
                float2 i1 = *(const float2*)&sAI[k * 128 + 64 + lane * 2];
                float2 j0 = *(const float2*)&sAJ[k * 128 +      lane * 2];
                float2 j1 = *(const float2*)&sAJ[k * 128 + 64 + lane * 2];
                float cc[4] = {c4.x, c4.y, c4.z, c4.w};
                float iv[2][2] = {{i0.x, i0.y}, {i1.x, i1.y}};
                float jv[2][2] = {{j0.x, j0.y}, {j1.x, j1.y}};
#pragma unroll
                for (int nd = 0; nd < 4; nd++)
#pragma unroll
                    for (int t = 0; t < 2; t++)
#pragma unroll
                        for (int c2 = 0; c2 < 2; c2++) {
                            ai[nd][t][c2] += cc[nd] * iv[t][c2];
                            aj[nd][t][c2] += cc[nd] * jv[t][c2];
                        }
            }
#pragma unroll
            for (int nd = 0; nd < 4; nd++)
#pragma unroll
                for (int t = 0; t < 2; t++)
#pragma unroll
                    for (int c2 = 0; c2 < 2; c2++) {
                        float a = sigm(ai[nd][t][c2] + aib[t][c2]);
                        float r = aj[nd][t][c2] + ajb[t][c2];
                        r = r > 0.f ? r : 0.f;
                        asum[nd][t][c2] += a * r;   // nd == batch index
                    }
        }
        __syncthreads();
    }

    // cross-warp reduce into POOL
#pragma unroll
    for (int nd = 0; nd < 4; nd++)
#pragma unroll
        for (int t = 0; t < 2; t++)
#pragma unroll
            for (int c2 = 0; c2 < 2; c2++)
                sC[(warp * 4 + nd) * 128 + (t * 64 + lane * 2 + c2)] = asum[nd][t][c2];
    __syncthreads();
    for (int i = tid; i < 512; i += 256) {
        int b = i >> 7, j = i & 127;
        float s = 0.f;
#pragma unroll
        for (int w = 0; w < 8; w++) s += sC[(w * 4 + b) * 128 + j];
        atomicAdd(&g_POOL[b * 128 + j], s);
    }
}

// ---------------- final head ----------------
__global__ void k_head(const float* __restrict__ mlp_w, const float* __restrict__ mlp_b,
                       const float* __restrict__ cw, const float* __restrict__ cb,
                       float* __restrict__ out) {
    __shared__ float pooled[512];
    __shared__ float st[1024];
    int tid = threadIdx.x;
    for (int i = tid; i < 512; i += 256) pooled[i] = fmaxf(g_POOL[i], 0.f);
    __syncthreads();
    float acc[4] = {0.f, 0.f, 0.f, 0.f};
    for (int k = 0; k < 128; k++) {
        float w = mlp_w[tid * 128 + k];
#pragma unroll
        for (int b = 0; b < 4; b++) acc[b] += pooled[b * 128 + k] * w;
    }
    float mb = mlp_b[tid];
#pragma unroll
    for (int b = 0; b < 4; b++) st[b * 256 + tid] = fmaxf(acc[b] + mb, 0.f);
    __syncthreads();
    if (tid < 128) {
        int w = tid >> 5, lane = tid & 31;
        float s = 0.f;
        for (int k = lane; k < 256; k += 32) s += st[w * 256 + k] * cw[k];
#pragma unroll
        for (int off = 16; off; off >>= 1) s += __shfl_xor_sync(0xffffffffu, s, off);
        if (lane == 0) out[w] = s + cb[0];
    }
}

// ---------------- launch ----------------
extern "C" void kernel_launch(void* const* d_in, const int* in_sizes, int n_in,
                              void* d_out, int out_size) {
    const float* cov    = (const float*)d_in[0];
    const float* nodes  = (const float*)d_in[1];
    const int*   edges  = (const int*)  d_in[2];
    const int*   c2l    = (const int*)  d_in[3];
    const float* ggc    = (const float*)d_in[4];
    const float* w_ih   = (const float*)d_in[5];
    const float* w_hh   = (const float*)d_in[6];
    const float* b_ih   = (const float*)d_in[7];
    const float* b_hh   = (const float*)d_in[8];
    const float* ai_w   = (const float*)d_in[9];
    const float* ai_b   = (const float*)d_in[10];
    const float* aj_w   = (const float*)d_in[11];
    const float* aj_b   = (const float*)d_in[12];
    const float* mlp_w  = (const float*)d_in[13];
    const float* mlp_b  = (const float*)d_in[14];
    const float* cw     = (const float*)d_in[15];
    const float* cb     = (const float*)d_in[16];
    float* out = (float*)d_out;

    const int smem_gru = 29184 * 4;     // 116736 B
    const int smem_att = 37376 * 4;     // 149504 B
    cudaFuncSetAttribute(k_gru, cudaFuncAttributeMaxDynamicSharedMemorySize, smem_gru);
    cudaFuncSetAttribute(k_att, cudaFuncAttributeMaxDynamicSharedMemorySize, smem_att);

    k_prep_P<<<240, 256>>>(ggc, w_ih);
    k_prep_T<<<176, 256>>>(w_hh, ai_w, aj_w);
    k_init<<<NN, 256>>>(nodes);
    k_cov<<<(BB * NLBL + 255) / 256, 256>>>(cov, c2l);

    int sel = 0;
    for (int l = 0; l < 5; l++) {
        k_zero_agg<<<RR * CC / 4 / 256, 256>>>();
        k_scatter<<<(EE * 64) / 256, 256>>>(edges, sel);
        k_gru<<<(NTILES + GRU_TILES - 1) / GRU_TILES, 256, smem_gru>>>(b_ih, b_hh, l, sel);
        sel ^= 1;
    }

    k_zero_pool<<<2, 256>>>();
    k_att<<<(NTILES + 7) / 8, 256, smem_att>>>(ai_b, aj_b, sel);
    k_head<<<1, 256>>>(mlp_w, mlp_b, cw, cb, out);
}

// round 4
// speedup vs baseline: 1.8074x; 1.8074x over previous
#include <cuda_runtime.h>
#include <math.h>

#define BB   4
#define NN   50000
#define CC   64
#define EE   800000
#define NLBL 10000
#define RR   (NN*BB)        /* 200000 GEMM rows (node,batch) */
#define ROWF (BB*CC)        /* 256 floats per node across batches */
#define NTILES (RR/32)      /* 6250 */

// ---------------- device scratch (no allocations allowed) ----------------
__device__ float g_X[2][RR*CC];     // ping-pong node state, 2 x 51.2MB
__device__ float g_X0[RR*CC];       // initial features (needed for attention)
__device__ float g_AGG[RR*CC];      // neighbor sums
__device__ float g_P[5*64*192];     // P[l] = ggc[l] @ w_ih^T, [k][j] layout
__device__ float g_WHH[64*192];     // w_hh^T, [k][j]
__device__ float g_AIW[128*128];    // ai_w^T, [k][j]
__device__ float g_AJW[128*128];    // aj_w^T, [k][j]
__device__ float g_POOL[512];       // att pooled sums [b][128]
// CSR by destination
__device__ int   g_cnt[NN];
__device__ int   g_off[NN];
__device__ int   g_cur[NN];
__device__ int   g_csr[EE];

__device__ __forceinline__ float sigm(float v) { return 1.0f / (1.0f + expf(-v)); }

// ---------------- prep kernels ----------------
__global__ void k_prep_P(const float* __restrict__ ggc, const float* __restrict__ w_ih) {
    int idx = blockIdx.x * 256 + threadIdx.x;
    if (idx >= 5 * 64 * 192) return;
    int l = idx / (64 * 192);
    int rem = idx % (64 * 192);
    int k = rem / 192, j = rem % 192;
    const float* a = ggc + (l * 64 + k) * 64;
    const float* w = w_ih + j * 64;
    float s = 0.f;
#pragma unroll 8
    for (int c = 0; c < 64; c++) s += a[c] * w[c];
    g_P[idx] = s;
}

__global__ void k_prep_T(const float* __restrict__ w_hh,
                         const float* __restrict__ ai_w,
                         const float* __restrict__ aj_w) {
    int idx = blockIdx.x * 256 + threadIdx.x;
    if (idx < 12288) {
        int k = idx / 192, j = idx % 192;
        g_WHH[idx] = w_hh[j * 64 + k];
    } else if (idx < 12288 + 16384) {
        int i = idx - 12288;
        int k = i / 128, j = i % 128;
        g_AIW[i] = ai_w[j * 128 + k];
    } else if (idx < 12288 + 32768) {
        int i = idx - 28672;
        int k = i / 128, j = i % 128;
        g_AJW[i] = aj_w[j * 128 + k];
    }
}

__global__ void k_init(const float* __restrict__ nodes) {
    int n = blockIdx.x;
    int t = threadIdx.x;          // 0..255 -> (b,c)
    int c = t & 63;
    float v = (c < 63) ? nodes[n * 63 + c] : 0.f;
    int idx = n * ROWF + t;
    g_X0[idx] = v;
    g_X[0][idx] = v;
}

__global__ void k_cov(const float* __restrict__ cov, const int* __restrict__ c2l) {
    int idx = blockIdx.x * 256 + threadIdx.x;
    if (idx >= BB * NLBL) return;
    int b = idx / NLBL, j = idx % NLBL;
    int lbl = c2l[j];
    float v = cov[idx];
    int pos = lbl * ROWF + b * 64 + 63;
    g_X0[pos] = v;
    g_X[0][pos] = v;
}

__global__ void k_zero_pool() {
    int idx = blockIdx.x * 256 + threadIdx.x;
    if (idx < 512) g_POOL[idx] = 0.f;
}

// ---------------- CSR build (once per launch) ----------------
__global__ void k_zero_cnt() {
    int i = blockIdx.x * 256 + threadIdx.x;
    if (i < NN) g_cnt[i] = 0;
}

__global__ void k_hist(const int* __restrict__ edges) {
    int e = blockIdx.x * 256 + threadIdx.x;
    if (e < EE) atomicAdd(&g_cnt[edges[EE + e]], 1);
}

// single block, 1024 threads: exclusive scan of g_cnt -> g_off, g_cur
__global__ void __launch_bounds__(1024, 1) k_scan() {
    __shared__ int sp[1024];
    const int CH = (NN + 1023) / 1024;   // 49
    int t = threadIdx.x;
    int b0 = t * CH;
    int s = 0;
    for (int i = 0; i < CH; i++) {
        int n = b0 + i;
        if (n < NN) s += g_cnt[n];
    }
    sp[t] = s;
    __syncthreads();
    for (int off = 1; off < 1024; off <<= 1) {
        int v = (t >= off) ? sp[t - off] : 0;
        __syncthreads();
        sp[t] += v;
        __syncthreads();
    }
    int base = sp[t] - s;     // exclusive prefix
    for (int i = 0; i < CH; i++) {
        int n = b0 + i;
        if (n < NN) {
            g_off[n] = base;
            g_cur[n] = base;
            base += g_cnt[n];
        }
    }
}

__global__ void k_fill(const int* __restrict__ edges) {
    int e = blockIdx.x * 256 + threadIdx.x;
    if (e >= EE) return;
    int dst = edges[EE + e];
    int pos = atomicAdd(&g_cur[dst], 1);
    g_csr[pos] = edges[e];
}

// ---------------- edge gather: AGG[dst] = sum_{src in CSR(dst)} X[src] ----------------
// 64 threads per dst node, each owns one float4 of the 1KB row. No atomics.
__global__ void __launch_bounds__(256, 8) k_gather(int sel) {
    unsigned gid = blockIdx.x * 256u + threadIdx.x;
    int node = gid >> 6;
    int q = (gid & 63) * 4;
    if (node >= NN) return;
    const float* __restrict__ X = g_X[sel];
    int beg = g_off[node];
    int cnt = g_cnt[node];
    float4 acc = make_float4(0.f, 0.f, 0.f, 0.f);
    int j = 0;
    for (; j + 2 <= cnt; j += 2) {
        int i0 = g_csr[beg + j];
        int i1 = g_csr[beg + j + 1];
        const float4 v0 = *(const float4*)(X + i0 * ROWF + q);
        const float4 v1 = *(const float4*)(X + i1 * ROWF + q);
        acc.x += v0.x; acc.y += v0.y; acc.z += v0.z; acc.w += v0.w;
        acc.x += v1.x; acc.y += v1.y; acc.z += v1.z; acc.w += v1.w;
    }
    if (j < cnt) {
        int i0 = g_csr[beg + j];
        const float4 v0 = *(const float4*)(X + i0 * ROWF + q);
        acc.x += v0.x; acc.y += v0.y; acc.z += v0.z; acc.w += v0.w;
    }
    *(float4*)(g_AGG + node * ROWF + q) = acc;
}

// ---------------- fused GGC+GRU layer: x_new = GRU(AGG @ P, x) ----------------
// tile: 32 rows x 192 cols, two GEMMs (gx from AGG, gh from x) fused, K=64.
// 256 threads: warp w owns local rows [w*4, w*4+4); lane owns cols lane*2+{0,1}+64t, t<3.
#define GRU_TILES 8
__global__ void __launch_bounds__(256, 1)
k_gru(const float* __restrict__ b_ih, const float* __restrict__ b_hh, int layer, int sel) {
    extern __shared__ float sm[];
    float* sP = sm;               // 64*192
    float* sW = sm + 12288;       // 64*192
    float* sA = sm + 24576;       // [64][36] aggT
    float* sX = sA + 64 * 36;     // [64][36] xT

    const float* P  = g_P + layer * 12288;
    const float* Xc = g_X[sel];
    float*       Xn = g_X[sel ^ 1];

    int tid = threadIdx.x, lane = tid & 31, warp = tid >> 5;

    for (int i = tid; i < 3072; i += 256) {
        ((float4*)sP)[i] = ((const float4*)P)[i];
        ((float4*)sW)[i] = ((const float4*)g_WHH)[i];
    }
    float bi[3][2], bh[3][2];
#pragma unroll
    for (int t = 0; t < 3; t++) {
        bi[t][0] = b_ih[64 * t + lane * 2];
        bi[t][1] = b_ih[64 * t + lane * 2 + 1];
        bh[t][0] = b_hh[64 * t + lane * 2];
        bh[t][1] = b_hh[64 * t + lane * 2 + 1];
    }
    __syncthreads();

    for (int it = 0; it < GRU_TILES; it++) {
        int tile = blockIdx.x * GRU_TILES + it;
        bool valid = tile < NTILES;
        int row0 = tile * 32;
        if (valid) {
#pragma unroll
            for (int iter = 0; iter < 2; iter++) {
                int k4 = warp + iter * 8;   // float4 chunk of k
                const float4 va = *(const float4*)(g_AGG + (row0 + lane) * CC + k4 * 4);
                const float4 vx = *(const float4*)(Xc    + (row0 + lane) * CC + k4 * 4);
                sA[(k4 * 4 + 0) * 36 + lane] = va.x;
                sA[(k4 * 4 + 1) * 36 + lane] = va.y;
                sA[(k4 * 4 + 2) * 36 + lane] = va.z;
                sA[(k4 * 4 + 3) * 36 + lane] = va.w;
                sX[(k4 * 4 + 0) * 36 + lane] = vx.x;
                sX[(k4 * 4 + 1) * 36 + lane] = vx.y;
                sX[(k4 * 4 + 2) * 36 + lane] = vx.z;
                sX[(k4 * 4 + 3) * 36 + lane] = vx.w;
            }
        }
        __syncthreads();
        if (valid) {
            float ax[4][3][2] = {};
            float ah[4][3][2] = {};
#pragma unroll 2
            for (int k = 0; k < 64; k++) {
                float4 a4 = *(const float4*)&sA[k * 36 + warp * 4];
                float4 x4 = *(const float4*)&sX[k * 36 + warp * 4];
                float2 p0 = *(const float2*)&sP[k * 192 +       lane * 2];
                float2 p1 = *(const float2*)&sP[k * 192 +  64 + lane * 2];
                float2 p2 = *(const float2*)&sP[k * 192 + 128 + lane * 2];
                float2 w0 = *(const float2*)&sW[k * 192 +       lane * 2];
                float2 w1 = *(const float2*)&sW[k * 192 +  64 + lane * 2];
                float2 w2 = *(const float2*)&sW[k * 192 + 128 + lane * 2];
                float aa[4] = {a4.x, a4.y, a4.z, a4.w};
                float xx[4] = {x4.x, x4.y, x4.z, x4.w};
                float pv[3][2] = {{p0.x, p0.y}, {p1.x, p1.y}, {p2.x, p2.y}};
                float wv[3][2] = {{w0.x, w0.y}, {w1.x, w1.y}, {w2.x, w2.y}};
#pragma unroll
                for (int nd = 0; nd < 4; nd++)
#pragma unroll
                    for (int t = 0; t < 3; t++)
#pragma unroll
                        for (int c2 = 0; c2 < 2; c2++) {
                            ax[nd][t][c2] += aa[nd] * pv[t][c2];
                            ah[nd][t][c2] += xx[nd] * wv[t][c2];
                        }
            }
#pragma unroll
            for (int nd = 0; nd < 4; nd++) {
                int row = row0 + warp * 4 + nd;
                float2 h2 = *(const float2*)&Xc[row * CC + lane * 2];
                float hv[2] = {h2.x, h2.y};
                float o[2];
#pragma unroll
                for (int c2 = 0; c2 < 2; c2++) {
                    float r  = sigm(ax[nd][0][c2] + bi[0][c2] + ah[nd][0][c2] + bh[0][c2]);
                    float z  = sigm(ax[nd][1][c2] + bi[1][c2] + ah[nd][1][c2] + bh[1][c2]);
                    float nn = tanhf(ax[nd][2][c2] + bi[2][c2] + r * (ah[nd][2][c2] + bh[2][c2]));
                    o[c2] = (1.f - z) * nn + z * hv[c2];
                }
                *(float2*)&Xn[row * CC + lane * 2] = make_float2(o[0], o[1]);
            }
        }
        __syncthreads();
    }
}

// ---------------- attention + pooling ----------------
// cat = [x, x0] (K=128); a_i = sigmoid(cat@ai_w^T+b), a_j = relu(cat@aj_w^T+b)
// POOL[b][j] += a_i*a_j summed over nodes. rows are (n*4+b) so b == local row % 4.
__global__ void __launch_bounds__(256, 1)
k_att(const float* __restrict__ ai_b, const float* __restrict__ aj_b, int sel) {
    extern __shared__ float sm[];
    float* sAI = sm;              // 128*128
    float* sAJ = sm + 16384;      // 128*128
    float* sC  = sm + 32768;      // [128][36] catT, reused for reduction (4096 < 4608)

    const float* Xf = g_X[sel];
    int tid = threadIdx.x, lane = tid & 31, warp = tid >> 5;

    for (int i = tid; i < 4096; i += 256) {
        ((float4*)sAI)[i] = ((const float4*)g_AIW)[i];
        ((float4*)sAJ)[i] = ((const float4*)g_AJW)[i];
    }
    float aib[2][2], ajb[2][2];
#pragma unroll
    for (int t = 0; t < 2; t++) {
        aib[t][0] = ai_b[64 * t + lane * 2];
        aib[t][1] = ai_b[64 * t + lane * 2 + 1];
        ajb[t][0] = aj_b[64 * t + lane * 2];
        ajb[t][1] = aj_b[64 * t + lane * 2 + 1];
    }
    float asum[4][2][2] = {};    // [b][t][c2]
    __syncthreads();

    for (int it = 0; it < 8; it++) {
        int tile = blockIdx.x * 8 + it;
        bool valid = tile < NTILES;
        int row0 = tile * 32;
        if (valid) {
#pragma unroll
            for (int iter = 0; iter < 4; iter++) {
                int k0 = (warp + iter * 8) * 4;     // 0..124
                float4 v = (k0 < 64)
                    ? *(const float4*)(Xf   + (row0 + lane) * CC + k0)
                    : *(const float4*)(g_X0 + (row0 + lane) * CC + k0 - 64);
                sC[(k0 + 0) * 36 + lane] = v.x;
                sC[(k0 + 1) * 36 + lane] = v.y;
                sC[(k0 + 2) * 36 + lane] = v.z;
                sC[(k0 + 3) * 36 + lane] = v.w;
            }
        }
        __syncthreads();
        if (valid) {
            float ai[4][2][2] = {};
            float aj[4][2][2] = {};
#pragma unroll 2
            for (int k = 0; k < 128; k++) {
                float4 c4 = *(const float4*)&sC[k * 36 + warp * 4];
                float2 i0 = *(const float2*)&sAI[k * 128 +      lane * 2];
                float2 i1 = *(const float2*)&sAI[k * 128 + 64 + lane * 2];
                float2 j0 = *(const float2*)&sAJ[k * 128 +      lane * 2];
                float2 j1 = *(const float2*)&sAJ[k * 128 + 64 + lane * 2];
                float cc[4] = {c4.x, c4.y, c4.z, c4.w};
                float iv[2][2] = {{i0.x, i0.y}, {i1.x, i1.y}};
                float jv[2][2] = {{j0.x, j0.y}, {j1.x, j1.y}};
#pragma unroll
                for (int nd = 0; nd < 4; nd++)
#pragma unroll
                    for (int t = 0; t < 2; t++)
#pragma unroll
                        for (int c2 = 0; c2 < 2; c2++) {
                            ai[nd][t][c2] += cc[nd] * iv[t][c2];
                            aj[nd][t][c2] += cc[nd] * jv[t][c2];
                        }
            }
#pragma unroll
            for (int nd = 0; nd < 4; nd++)
#pragma unroll
                for (int t = 0; t < 2; t++)
#pragma unroll
                    for (int c2 = 0; c2 < 2; c2++) {
                        float a = sigm(ai[nd][t][c2] + aib[t][c2]);
                        float r = aj[nd][t][c2] + ajb[t][c2];
                        r = r > 0.f ? r : 0.f;
                        asum[nd][t][c2] += a * r;   // nd == batch index
                    }
        }
        __syncthreads();
    }

    // cross-warp reduce into POOL
#pragma unroll
    for (int nd = 0; nd < 4; nd++)
#pragma unroll
        for (int t = 0; t < 2; t++)
#pragma unroll
            for (int c2 = 0; c2 < 2; c2++)
                sC[(warp * 4 + nd) * 128 + (t * 64 + lane * 2 + c2)] = asum[nd][t][c2];
    __syncthreads();
    for (int i = tid; i < 512; i += 256) {
        int b = i >> 7, j = i & 127;
        float s = 0.f;
#pragma unroll
        for (int w = 0; w < 8; w++) s += sC[(w * 4 + b) * 128 + j];
        atomicAdd(&g_POOL[b * 128 + j], s);
    }
}

// ---------------- final head ----------------
__global__ void k_head(const float* __restrict__ mlp_w, const float* __restrict__ mlp_b,
                       const float* __restrict__ cw, const float* __restrict__ cb,
                       float* __restrict__ out) {
    __shared__ float pooled[512];
    __shared__ float st[1024];
    int tid = threadIdx.x;
    for (int i = tid; i < 512; i += 256) pooled[i] = fmaxf(g_POOL[i], 0.f);
    __syncthreads();
    float acc[4] = {0.f, 0.f, 0.f, 0.f};
    for (int k = 0; k < 128; k++) {
        float w = mlp_w[tid * 128 + k];
#pragma unroll
        for (int b = 0; b < 4; b++) acc[b] += pooled[b * 128 + k] * w;
    }
    float mb = mlp_b[tid];
#pragma unroll
    for (int b = 0; b < 4; b++) st[b * 256 + tid] = fmaxf(acc[b] + mb, 0.f);
    __syncthreads();
    if (tid < 128) {
        int w = tid >> 5, lane = tid & 31;
        float s = 0.f;
        for (int k = lane; k < 256; k += 32) s += st[w * 256 + k] * cw[k];
#pragma unroll
        for (int off = 16; off; off >>= 1) s += __shfl_xor_sync(0xffffffffu, s, off);
        if (lane == 0) out[w] = s + cb[0];
    }
}

// ---------------- launch ----------------
extern "C" void kernel_launch(void* const* d_in, const int* in_sizes, int n_in,
                              void* d_out, int out_size) {
    const float* cov    = (const float*)d_in[0];
    const float* nodes  = (const float*)d_in[1];
    const int*   edges  = (const int*)  d_in[2];
    const int*   c2l    = (const int*)  d_in[3];
    const float* ggc    = (const float*)d_in[4];
    const float* w_ih   = (const float*)d_in[5];
    const float* w_hh   = (const float*)d_in[6];
    const float* b_ih   = (const float*)d_in[7];
    const float* b_hh   = (const float*)d_in[8];
    const float* ai_w   = (const float*)d_in[9];
    const float* ai_b   = (const float*)d_in[10];
    const float* aj_w   = (const float*)d_in[11];
    const float* aj_b   = (const float*)d_in[12];
    const float* mlp_w  = (const float*)d_in[13];
    const float* mlp_b  = (const float*)d_in[14];
    const float* cw     = (const float*)d_in[15];
    const float* cb     = (const float*)d_in[16];
    float* out = (float*)d_out;

    const int smem_gru = 29184 * 4;     // 116736 B
    const int smem_att = 37376 * 4;     // 149504 B
    cudaFuncSetAttribute(k_gru, cudaFuncAttributeMaxDynamicSharedMemorySize, smem_gru);
    cudaFuncSetAttribute(k_att, cudaFuncAttributeMaxDynamicSharedMemorySize, smem_att);

    // prep + CSR build (independent of layer loop)
    k_prep_P<<<240, 256>>>(ggc, w_ih);
    k_prep_T<<<176, 256>>>(w_hh, ai_w, aj_w);
    k_init<<<NN, 256>>>(nodes);
    k_cov<<<(BB * NLBL + 255) / 256, 256>>>(cov, c2l);

    k_zero_cnt<<<(NN + 255) / 256, 256>>>();
    k_hist<<<(EE + 255) / 256, 256>>>(edges);
    k_scan<<<1, 1024>>>();
    k_fill<<<(EE + 255) / 256, 256>>>(edges);

    int sel = 0;
    for (int l = 0; l < 5; l++) {
        k_gather<<<(NN * 64 + 255) / 256, 256>>>(sel);
        k_gru<<<(NTILES + GRU_TILES - 1) / GRU_TILES, 256, smem_gru>>>(b_ih, b_hh, l, sel);
        sel ^= 1;
    }

    k_zero_pool<<<2, 256>>>();
    k_att<<<(NTILES + 7) / 8, 256, smem_att>>>(ai_b, aj_b, sel);
    k_head<<<1, 256>>>(mlp_w, mlp_b, cw, cb, out);
}